// round 8
// baseline (speedup 1.0000x reference)
#include <cuda_runtime.h>
#include <cuda_bf16.h>
#include <math.h>
#include <stdint.h>
#include <stddef.h>

#define BB   2
#define N0   4096
#define N1   1024
#define N2   256
#define KNN  20
#define AA   12

#define C0   32
#define C1   64
#define C2   128
#define C3   256
#define C4   512

#define NSLICE 32

#define INF_F __int_as_float(0x7f800000)

// ---------------- scratch (device globals; no runtime allocation) ----------------
__device__ float d_fm0 [BB*N0*C0*AA];
__device__ float d_fm1 [BB*N0*C1*AA];
__device__ float d_fmp1[BB*N1*C1*AA];
__device__ float d_fm2 [BB*N1*C2*AA];
__device__ float d_fm3 [BB*N1*C3*AA];
__device__ float d_fmp2[BB*N2*C3*AA];
__device__ float d_fm4 [BB*N2*C4*AA];
__device__ float d_gbuf [BB*N0*C1*AA];
__device__ float d_fcbuf[BB*N0*C1*AA];
__device__ int   d_idx0[BB*N0*KNN];
__device__ int   d_idx1[BB*N1*KNN];
__device__ int   d_idx2[BB*N2*KNN];
__device__ float d_v1[BB*N1*3];
__device__ float d_v2[BB*N2*3];
__device__ float d_bnscale[C4];
__device__ float d_bnshift[C4];
__device__ double d_bnpart[NSLICE*C3*2];

// ---------------- packed fp32x2 helpers ----------------
__device__ __forceinline__ unsigned long long pack2(float lo, float hi) {
    unsigned long long r;
    asm("mov.b64 %0, {%1, %2};" : "=l"(r) : "f"(lo), "f"(hi));
    return r;
}
__device__ __forceinline__ unsigned long long fma2(unsigned long long a,
                                                   unsigned long long b,
                                                   unsigned long long c) {
    unsigned long long d;
    asm("fma.rn.f32x2 %0, %1, %2, %3;" : "=l"(d) : "l"(a), "l"(b), "l"(c));
    return d;
}

// ---------------- KNN: top-(k+1) by (dist, idx), drop first ----------------
__global__ void knn_kernel(const float* __restrict__ v, int* __restrict__ idx, int npts) {
    int b = blockIdx.y;
    int q = blockIdx.x * 64 + threadIdx.x;
    const float* vb = v + (size_t)b * npts * 3;

    bool active = (q < npts);
    float qx = 0.f, qy = 0.f, qz = 0.f, qd2 = 0.f;
    if (active) {
        qx = vb[q*3+0]; qy = vb[q*3+1]; qz = vb[q*3+2];
        qd2 = qx*qx + qy*qy + qz*qz;
    }

    float bd[KNN+1];
    int   bi[KNN+1];
#pragma unroll
    for (int i = 0; i <= KNN; i++) { bd[i] = INF_F; bi[i] = -1; }
    float worst = INF_F;

    __shared__ float sx[128], sy[128], sz[128], sd2[128];

    for (int tile = 0; tile < npts; tile += 128) {
#pragma unroll
        for (int rep = 0; rep < 2; rep++) {
            int jj = threadIdx.x + rep*64;
            int j = tile + jj;
            if (j < npts) {
                float x = vb[j*3+0], y = vb[j*3+1], z = vb[j*3+2];
                sx[jj] = x; sy[jj] = y; sz[jj] = z;
                sd2[jj] = x*x + y*y + z*z;
            }
        }
        __syncthreads();
        int cnt = npts - tile; if (cnt > 128) cnt = 128;
        if (active) {
#pragma unroll 4
            for (int jj = 0; jj < cnt; jj++) {
                float dot  = qx*sx[jj] + qy*sy[jj] + qz*sz[jj];
                float dist = (qd2 + sd2[jj]) - 2.0f*dot;
                if (dist < worst) {
                    int p = KNN;
                    while (p > 0 && bd[p-1] > dist) {
                        bd[p] = bd[p-1]; bi[p] = bi[p-1]; p--;
                    }
                    bd[p] = dist; bi[p] = tile + jj;
                    worst = bd[KNN];
                }
            }
        }
        __syncthreads();
    }
    if (active) {
        int* op = idx + ((size_t)b*npts + q) * KNN;
#pragma unroll
        for (int j = 0; j < KNN; j++) op[j] = bi[j+1];
    }
}

// ---------------- conv_surface (+ fused fea0) ----------------
__global__ void conv_surface_kernel(const float* __restrict__ v, const int* __restrict__ idx,
                                    const float* __restrict__ K0, float* __restrict__ fm0,
                                    float* __restrict__ fea_out) {
    int node = blockIdx.x;
    int t = threadIdx.x;                   // 384 = C0*AA
    __shared__ float sdir[KNN][3];
    __shared__ float sK0[C0*AA*3];
    __shared__ float sred[C0*AA];

    for (int i = t; i < C0*AA*3; i += blockDim.x) sK0[i] = K0[i];
    if (t < KNN) {
        int m = idx[(size_t)node*KNN + t];
        int b = node / N0;
        const float* pn = v + (size_t)node * 3;
        const float* pm = v + ((size_t)b*N0 + m) * 3;
        float dx = pm[0]-pn[0], dy = pm[1]-pn[1], dz = pm[2]-pn[2];
        float den = sqrtf(dx*dx + dy*dy + dz*dz) + 1e-8f;
        sdir[t][0] = dx/den; sdir[t][1] = dy/den; sdir[t][2] = dz/den;
    }
    __syncthreads();

    float kx = sK0[t*3+0], ky = sK0[t*3+1], kz = sK0[t*3+2];
    float m = 0.0f;
#pragma unroll
    for (int k = 0; k < KNN; k++) {
        float d = sdir[k][0]*kx + sdir[k][1]*ky + sdir[k][2]*kz;
        m = fmaxf(m, d);
    }
    fm0[(size_t)node * (C0*AA) + t] = m;
    sred[t] = m;
    __syncthreads();
    if (t < C0) {                          // fea: max over a (12)
        float r = sred[t*AA];
#pragma unroll
        for (int a = 1; a < AA; a++) r = fmaxf(r, sred[t*AA + a]);
        fea_out[node * C0 + t] = r;        // out[b,n,c] layout == node*C0+c
    }
}

// ---------------- proj (single-node items, Ws/Wc split, packed f32x2) ----------------
// item = (o, node, wsel). 6 f32x2 accumulators/thread -> low regs, high occ.
// Accumulation order over c identical to reference summation order.
template<int CIN, int COUT, int NB>
__global__ void proj_t_kernel(const float* __restrict__ fm,
                              const float* __restrict__ Ws, const float* __restrict__ Wc,
                              const float* __restrict__ bc,
                              float* __restrict__ g, float* __restrict__ fc) {
    __shared__ __align__(16) float sf[NB*CIN*AA];
    int t = threadIdx.x;                   // 512
    size_t nbase = (size_t)blockIdx.x * NB;

    {
        const float4* src = (const float4*)(fm + nbase * CIN * AA);
        float4* dst = (float4*)sf;
        const int TOT4 = NB*CIN*AA/4;
        for (int i = t; i < TOT4; i += blockDim.x) dst[i] = src[i];
    }
    __syncthreads();

    const int NITEMS = COUT * NB * 2;
    for (int item = t; item < NITEMS; item += blockDim.x) {
        int o    = item % COUT;
        int r    = item / COUT;
        int node = r % NB;
        int wsel = r / NB;                 // 0: Ws->g, 1: Wc->fc(+bias)
        const float* W = wsel ? Wc : Ws;
        const float* sfn = sf + node * CIN * AA;

        float b0 = wsel ? bc[o] : 0.0f;
        unsigned long long acc[6];
        unsigned long long bp = pack2(b0, b0);
#pragma unroll
        for (int j = 0; j < 6; j++) acc[j] = bp;

#pragma unroll 2
        for (int c = 0; c < CIN; c++) {
            float w = W[c*COUT + o];
            unsigned long long w2 = pack2(w, w);
            const ulonglong2* f = (const ulonglong2*)(sfn + c*AA);
            ulonglong2 a0 = f[0], a1 = f[1], a2 = f[2];
            acc[0] = fma2(a0.x, w2, acc[0]);
            acc[1] = fma2(a0.y, w2, acc[1]);
            acc[2] = fma2(a1.x, w2, acc[2]);
            acc[3] = fma2(a1.y, w2, acc[3]);
            acc[4] = fma2(a2.x, w2, acc[4]);
            acc[5] = fma2(a2.y, w2, acc[5]);
        }

        float* dst = (wsel ? fc : g) + ((nbase + node)*COUT + o)*AA;
        unsigned long long* dp = (unsigned long long*)dst;
#pragma unroll
        for (int j = 0; j < 6; j++) dp[j] = acc[j];
    }
}

// ---------------- neighbor: out = fc + max_k g[idx_k]*theta_k (float4 gathers) ----------------
__global__ void neighbor_kernel(const float* __restrict__ g, const float* __restrict__ fc,
                                const float* __restrict__ v, const int* __restrict__ idx,
                                const float* __restrict__ dirs,
                                float* __restrict__ out, int npts, int cout) {
    int node = blockIdx.x;
    int b = node / npts;
    int t = threadIdx.x;
    __shared__ float sdir[KNN][3];
    __shared__ float sth[KNN][AA];
    __shared__ int   sidx[KNN];
    __shared__ float sdv[AA*3];

    if (t < AA*3) sdv[t] = dirs[t];
    if (t < KNN) {
        int m = idx[(size_t)node*KNN + t];
        sidx[t] = m;
        const float* pn = v + (size_t)node * 3;
        const float* pm = v + ((size_t)b*npts + m) * 3;
        float dx = pm[0]-pn[0], dy = pm[1]-pn[1], dz = pm[2]-pn[2];
        float den = sqrtf(dx*dx + dy*dy + dz*dz) + 1e-8f;
        sdir[t][0] = dx/den; sdir[t][1] = dy/den; sdir[t][2] = dz/den;
    }
    __syncthreads();
    if (t < KNN*AA) {
        int k = t / AA, a = t % AA;
        float d = sdir[k][0]*sdv[a*3+0] + sdir[k][1]*sdv[a*3+1] + sdir[k][2]*sdv[a*3+2];
        sth[k][a] = fmaxf(d, 0.0f);
    }
    __syncthreads();

    int tot = cout * AA;
    int tot4 = tot / 4;
    size_t out_off = (size_t)node * tot;
    for (int q = t; q < tot4; q += blockDim.x) {
        int base = q * 4;
        int a0 = base % AA;
        float4 m = make_float4(-INF_F, -INF_F, -INF_F, -INF_F);
#pragma unroll
        for (int k = 0; k < KNN; k++) {
            const float4 gv = *(const float4*)(g + ((size_t)b*npts + sidx[k])*tot + base);
            const float4 th = *(const float4*)(&sth[k][a0]);
            m.x = fmaxf(m.x, gv.x*th.x);
            m.y = fmaxf(m.y, gv.y*th.y);
            m.z = fmaxf(m.z, gv.z*th.z);
            m.w = fmaxf(m.w, gv.w*th.w);
        }
        float4 f = *(const float4*)(fc + out_off + base);
        *(float4*)(out + out_off + base) =
            make_float4(f.x+m.x, f.y+m.y, f.z+m.z, f.w+m.w);
    }
}

// ---------------- batchnorm stats: stage 1 (partial sums per slice) ----------------
__global__ void bn_part_kernel(const float* __restrict__ x, double* __restrict__ part,
                               int C, int npts) {
    int c = blockIdx.x;
    int s = blockIdx.y;
    int t = threadIdx.x;
    int nn = BB * npts;
    int nps = nn / NSLICE;
    double sm = 0.0, s2 = 0.0;
    for (int i = s*nps + t; i < (s+1)*nps; i += blockDim.x) {
        const float4* p = (const float4*)(x + ((size_t)i * C + c) * AA);
#pragma unroll
        for (int h = 0; h < 3; h++) {
            float4 v = p[h];
            double a = v.x, b = v.y, d = v.z, e = v.w;
            sm += a + b + d + e;
            s2 += a*a + b*b + d*d + e*e;
        }
    }
    __shared__ double sh[64], sh2[64];
    sh[t] = sm; sh2[t] = s2;
    __syncthreads();
    for (int st = 32; st > 0; st >>= 1) {
        if (t < st) { sh[t] += sh[t+st]; sh2[t] += sh2[t+st]; }
        __syncthreads();
    }
    if (t == 0) {
        part[(s*C + c)*2 + 0] = sh[0];
        part[(s*C + c)*2 + 1] = sh2[0];
    }
}

// ---------------- batchnorm stats: stage 2 (finalize scale/shift) ----------------
__global__ void bn_finalize_kernel(const double* __restrict__ part,
                                   const float* __restrict__ gamma, const float* __restrict__ beta,
                                   float* __restrict__ scale, float* __restrict__ shift,
                                   int C, int npts) {
    int c = threadIdx.x;
    if (c >= C) return;
    double s = 0.0, s2 = 0.0;
    for (int sl = 0; sl < NSLICE; sl++) {
        s  += part[(sl*C + c)*2 + 0];
        s2 += part[(sl*C + c)*2 + 1];
    }
    double cnt = (double)BB * npts * AA;
    double mean = s / cnt;
    double var  = s2 / cnt - mean * mean;
    float sc = gamma[c] * (float)(1.0 / sqrt(var + 1e-5));
    scale[c] = sc;
    shift[c] = beta[c] - (float)mean * sc;
}

// ---------------- fused bn apply + relu + fea (max over a) ----------------
__global__ void bn_fea_kernel(float* __restrict__ x,
                              const float* __restrict__ scale, const float* __restrict__ shift,
                              float* __restrict__ out, int C, int total_nc) {
    int i = blockIdx.x * blockDim.x + threadIdx.x;
    if (i >= total_nc) return;
    int c = i % C;
    float sc = scale[c], sh = shift[c];
    float4* p = (float4*)(x + (size_t)i * AA);
    float m = 0.0f;
#pragma unroll
    for (int j = 0; j < 3; j++) {
        float4 v = p[j];
        v.x = fmaxf(v.x*sc + sh, 0.f);
        v.y = fmaxf(v.y*sc + sh, 0.f);
        v.z = fmaxf(v.z*sc + sh, 0.f);
        v.w = fmaxf(v.w*sc + sh, 0.f);
        p[j] = v;
        m = fmaxf(m, fmaxf(fmaxf(v.x, v.y), fmaxf(v.z, v.w)));
    }
    out[i] = m;
}

// ---------------- pool ----------------
__global__ void pool_kernel(const float* __restrict__ v, const float* __restrict__ fm,
                            const int* __restrict__ idx,
                            float* __restrict__ v_out, float* __restrict__ fm_out,
                            int npts, int C) {
    int nsel = npts / 4;
    int bs = blockIdx.x;
    int b = bs / nsel, s = bs % nsel;
    int n = s * 4;
    size_t node = (size_t)b * npts + n;
    int t = threadIdx.x;
    __shared__ int sidx[4];
    if (t < 4) sidx[t] = idx[node*KNN + t];
    if (t < 3) v_out[((size_t)b*nsel + s)*3 + t] = v[node*3 + t];
    __syncthreads();
    int tot = C * AA;
    for (int i = t; i < tot; i += blockDim.x) {
        float m = fm[node*tot + i];
#pragma unroll
        for (int k = 0; k < 4; k++)
            m = fmaxf(m, fm[((size_t)b*npts + sidx[k])*tot + i]);
        fm_out[((size_t)b*nsel + s)*tot + i] = m;
    }
}

// ---------------- fea (no-BN layers) ----------------
__global__ void fea_kernel(const float* __restrict__ fm, float* __restrict__ out,
                           int C, int npts) {
    int i = blockIdx.x * blockDim.x + threadIdx.x;
    int total = BB * npts * C;
    if (i >= total) return;
    const float* p = fm + (size_t)i * AA;
    float m = p[0];
#pragma unroll
    for (int a = 1; a < AA; a++) m = fmaxf(m, p[a]);
    out[i] = m;
}

// ---------------- launch ----------------
extern "C" void kernel_launch(void* const* d_in, const int* in_sizes, int n_in,
                              void* d_out, int out_size) {
    const float* vertices = (const float*)d_in[0];
    const float* K0    = (const float*)d_in[1];
    const float* dirs1 = (const float*)d_in[2];
    const float* Wc1   = (const float*)d_in[3];
    const float* bc1   = (const float*)d_in[4];
    const float* Ws1   = (const float*)d_in[5];
    const float* dirs2 = (const float*)d_in[6];
    const float* Wc2   = (const float*)d_in[7];
    const float* bc2   = (const float*)d_in[8];
    const float* Ws2   = (const float*)d_in[9];
    const float* dirs3 = (const float*)d_in[10];
    const float* Wc3   = (const float*)d_in[11];
    const float* bc3   = (const float*)d_in[12];
    const float* Ws3   = (const float*)d_in[13];
    const float* dirs4 = (const float*)d_in[14];
    const float* Wc4   = (const float*)d_in[15];
    const float* bc4   = (const float*)d_in[16];
    const float* Ws4   = (const float*)d_in[17];
    const float* g1 = (const float*)d_in[18];
    const float* b1 = (const float*)d_in[19];
    const float* g2 = (const float*)d_in[20];
    const float* b2 = (const float*)d_in[21];
    const float* g3 = (const float*)d_in[22];
    const float* b3 = (const float*)d_in[23];
    float* out = (float*)d_out;

    float *fm0, *fm1, *fmp1, *fm2, *fm3, *fmp2, *fm4, *gbuf, *fcbuf, *v1, *v2, *bnscale, *bnshift;
    double *bnpart;
    int *idx0, *idx1, *idx2;
    cudaGetSymbolAddress((void**)&fm0,  d_fm0);
    cudaGetSymbolAddress((void**)&fm1,  d_fm1);
    cudaGetSymbolAddress((void**)&fmp1, d_fmp1);
    cudaGetSymbolAddress((void**)&fm2,  d_fm2);
    cudaGetSymbolAddress((void**)&fm3,  d_fm3);
    cudaGetSymbolAddress((void**)&fmp2, d_fmp2);
    cudaGetSymbolAddress((void**)&fm4,  d_fm4);
    cudaGetSymbolAddress((void**)&gbuf, d_gbuf);
    cudaGetSymbolAddress((void**)&fcbuf,d_fcbuf);
    cudaGetSymbolAddress((void**)&idx0, d_idx0);
    cudaGetSymbolAddress((void**)&idx1, d_idx1);
    cudaGetSymbolAddress((void**)&idx2, d_idx2);
    cudaGetSymbolAddress((void**)&v1,   d_v1);
    cudaGetSymbolAddress((void**)&v2,   d_v2);
    cudaGetSymbolAddress((void**)&bnscale, d_bnscale);
    cudaGetSymbolAddress((void**)&bnshift, d_bnshift);
    cudaGetSymbolAddress((void**)&bnpart,  d_bnpart);

    const size_t off0 = 0;
    const size_t off1 = off0 + (size_t)BB*N0*C0;
    const size_t off2 = off1 + (size_t)BB*N0*C1;
    const size_t off3 = off2 + (size_t)BB*N1*C2;
    const size_t off4 = off3 + (size_t)BB*N1*C3;

    // ---- stage 0 (fea0 fused into conv_surface) ----
    knn_kernel<<<dim3(N0/64, BB), 64>>>(vertices, idx0, N0);
    conv_surface_kernel<<<BB*N0, C0*AA>>>(vertices, idx0, K0, fm0, out + off0);

    // ---- layer 1: 32 -> 64 on 4096 ----
    proj_t_kernel<C0, C1, 16><<<(BB*N0)/16, 512>>>(fm0, Ws1, Wc1, bc1, gbuf, fcbuf);
    neighbor_kernel<<<BB*N0, 256>>>(gbuf, fcbuf, vertices, idx0, dirs1, fm1, N0, C1);
    bn_part_kernel<<<dim3(C1, NSLICE), 64>>>(fm1, bnpart, C1, N0);
    bn_finalize_kernel<<<1, 256>>>(bnpart, g1, b1, bnscale, bnshift, C1, N0);
    bn_fea_kernel<<<(BB*N0*C1 + 255)/256, 256>>>(fm1, bnscale, bnshift, out + off1, C1, BB*N0*C1);

    // ---- pool 1 + knn on 1024 ----
    pool_kernel<<<BB*N1, 256>>>(vertices, fm1, idx0, v1, fmp1, N0, C1);
    knn_kernel<<<dim3(N1/64, BB), 64>>>(v1, idx1, N1);

    // ---- layer 2: 64 -> 128 on 1024 ----
    proj_t_kernel<C1, C2, 8><<<(BB*N1)/8, 512>>>(fmp1, Ws2, Wc2, bc2, gbuf, fcbuf);
    neighbor_kernel<<<BB*N1, 256>>>(gbuf, fcbuf, v1, idx1, dirs2, fm2, N1, C2);
    bn_part_kernel<<<dim3(C2, NSLICE), 64>>>(fm2, bnpart, C2, N1);
    bn_finalize_kernel<<<1, 256>>>(bnpart, g2, b2, bnscale, bnshift, C2, N1);
    bn_fea_kernel<<<(BB*N1*C2 + 255)/256, 256>>>(fm2, bnscale, bnshift, out + off2, C2, BB*N1*C2);

    // ---- layer 3: 128 -> 256 on 1024 ----
    proj_t_kernel<C2, C3, 4><<<(BB*N1)/4, 512>>>(fm2, Ws3, Wc3, bc3, gbuf, fcbuf);
    neighbor_kernel<<<BB*N1, 256>>>(gbuf, fcbuf, v1, idx1, dirs3, fm3, N1, C3);
    bn_part_kernel<<<dim3(C3, NSLICE), 64>>>(fm3, bnpart, C3, N1);
    bn_finalize_kernel<<<1, 256>>>(bnpart, g3, b3, bnscale, bnshift, C3, N1);
    bn_fea_kernel<<<(BB*N1*C3 + 255)/256, 256>>>(fm3, bnscale, bnshift, out + off3, C3, BB*N1*C3);

    // ---- pool 2 + knn on 256 ----
    pool_kernel<<<BB*N2, 256>>>(v1, fm3, idx1, v2, fmp2, N1, C3);
    knn_kernel<<<dim3(N2/64, BB), 64>>>(v2, idx2, N2);

    // ---- layer 4: 256 -> 512 on 256 (no BN/relu) ----
    proj_t_kernel<C3, C4, 2><<<(BB*N2)/2, 512>>>(fmp2, Ws4, Wc4, bc4, gbuf, fcbuf);
    neighbor_kernel<<<BB*N2, 256>>>(gbuf, fcbuf, v2, idx2, dirs4, fm4, N2, C4);
    fea_kernel<<<(BB*N2*C4 + 255)/256, 256>>>(fm4, out + off4, C4, N2);
}

// round 9
// speedup vs baseline: 1.0814x; 1.0814x over previous
#include <cuda_runtime.h>
#include <cuda_bf16.h>
#include <math.h>
#include <stdint.h>
#include <stddef.h>

#define BB   2
#define N0   4096
#define N1   1024
#define N2   256
#define KNN  20
#define AA   12

#define C0   32
#define C1   64
#define C2   128
#define C3   256
#define C4   512

#define NSLICE 32

#define INF_F __int_as_float(0x7f800000)

// ---------------- scratch (device globals; no runtime allocation) ----------------
__device__ float d_fm0 [BB*N0*C0*AA];
__device__ float d_fm1 [BB*N0*C1*AA];
__device__ float d_fmp1[BB*N1*C1*AA];
__device__ float d_fm2 [BB*N1*C2*AA];
__device__ float d_fm3 [BB*N1*C3*AA];
__device__ float d_fmp2[BB*N2*C3*AA];
__device__ float d_fm4 [BB*N2*C4*AA];
__device__ float d_gbuf [BB*N0*C1*AA];
__device__ float d_fcbuf[BB*N0*C1*AA];
__device__ int   d_idx0[BB*N0*KNN];
__device__ int   d_idx1[BB*N1*KNN];
__device__ int   d_idx2[BB*N2*KNN];
__device__ float d_v1[BB*N1*3];
__device__ float d_v2[BB*N2*3];
__device__ float d_bnscale[C4];
__device__ float d_bnshift[C4];
__device__ double d_bnpart[NSLICE*C3*2];

// ---------------- packed fp32x2 helpers ----------------
__device__ __forceinline__ unsigned long long pack2(float lo, float hi) {
    unsigned long long r;
    asm("mov.b64 %0, {%1, %2};" : "=l"(r) : "f"(lo), "f"(hi));
    return r;
}
__device__ __forceinline__ unsigned long long fma2(unsigned long long a,
                                                   unsigned long long b,
                                                   unsigned long long c) {
    unsigned long long d;
    asm("fma.rn.f32x2 %0, %1, %2, %3;" : "=l"(d) : "l"(a), "l"(b), "l"(c));
    return d;
}

// ---------------- KNN: top-(k+1) by (dist, idx), drop first ----------------
__global__ void knn_kernel(const float* __restrict__ v, int* __restrict__ idx, int npts) {
    int b = blockIdx.y;
    int q = blockIdx.x * 64 + threadIdx.x;
    const float* vb = v + (size_t)b * npts * 3;

    bool active = (q < npts);
    float qx = 0.f, qy = 0.f, qz = 0.f, qd2 = 0.f;
    if (active) {
        qx = vb[q*3+0]; qy = vb[q*3+1]; qz = vb[q*3+2];
        qd2 = qx*qx + qy*qy + qz*qz;
    }

    float bd[KNN+1];
    int   bi[KNN+1];
#pragma unroll
    for (int i = 0; i <= KNN; i++) { bd[i] = INF_F; bi[i] = -1; }
    float worst = INF_F;

    __shared__ float sx[128], sy[128], sz[128], sd2[128];

    for (int tile = 0; tile < npts; tile += 128) {
#pragma unroll
        for (int rep = 0; rep < 2; rep++) {
            int jj = threadIdx.x + rep*64;
            int j = tile + jj;
            if (j < npts) {
                float x = vb[j*3+0], y = vb[j*3+1], z = vb[j*3+2];
                sx[jj] = x; sy[jj] = y; sz[jj] = z;
                sd2[jj] = x*x + y*y + z*z;
            }
        }
        __syncthreads();
        int cnt = npts - tile; if (cnt > 128) cnt = 128;
        if (active) {
#pragma unroll 4
            for (int jj = 0; jj < cnt; jj++) {
                float dot  = qx*sx[jj] + qy*sy[jj] + qz*sz[jj];
                float dist = (qd2 + sd2[jj]) - 2.0f*dot;
                if (dist < worst) {
                    int p = KNN;
                    while (p > 0 && bd[p-1] > dist) {
                        bd[p] = bd[p-1]; bi[p] = bi[p-1]; p--;
                    }
                    bd[p] = dist; bi[p] = tile + jj;
                    worst = bd[KNN];
                }
            }
        }
        __syncthreads();
    }
    if (active) {
        int* op = idx + ((size_t)b*npts + q) * KNN;
#pragma unroll
        for (int j = 0; j < KNN; j++) op[j] = bi[j+1];
    }
}

// ---------------- conv_surface (+ fused fea0) ----------------
__global__ void conv_surface_kernel(const float* __restrict__ v, const int* __restrict__ idx,
                                    const float* __restrict__ K0, float* __restrict__ fm0,
                                    float* __restrict__ fea_out) {
    int node = blockIdx.x;
    int t = threadIdx.x;                   // 384 = C0*AA
    __shared__ float sdir[KNN][3];
    __shared__ float sK0[C0*AA*3];
    __shared__ float sred[C0*AA];

    for (int i = t; i < C0*AA*3; i += blockDim.x) sK0[i] = K0[i];
    if (t < KNN) {
        int m = idx[(size_t)node*KNN + t];
        int b = node / N0;
        const float* pn = v + (size_t)node * 3;
        const float* pm = v + ((size_t)b*N0 + m) * 3;
        float dx = pm[0]-pn[0], dy = pm[1]-pn[1], dz = pm[2]-pn[2];
        float den = sqrtf(dx*dx + dy*dy + dz*dz) + 1e-8f;
        sdir[t][0] = dx/den; sdir[t][1] = dy/den; sdir[t][2] = dz/den;
    }
    __syncthreads();

    float kx = sK0[t*3+0], ky = sK0[t*3+1], kz = sK0[t*3+2];
    float m = 0.0f;
#pragma unroll
    for (int k = 0; k < KNN; k++) {
        float d = sdir[k][0]*kx + sdir[k][1]*ky + sdir[k][2]*kz;
        m = fmaxf(m, d);
    }
    fm0[(size_t)node * (C0*AA) + t] = m;
    sred[t] = m;
    __syncthreads();
    if (t < C0) {
        float r = sred[t*AA];
#pragma unroll
        for (int a = 1; a < AA; a++) r = fmaxf(r, sred[t*AA + a]);
        fea_out[node * C0 + t] = r;
    }
}

// ---------------- proj (R6 pair version: fused single pass, packed f32x2) ----------------
template<int CIN, int COUT, int NB>
__global__ void proj_t_kernel(const float* __restrict__ fm,
                              const float* __restrict__ Ws, const float* __restrict__ Wc,
                              const float* __restrict__ bc,
                              float* __restrict__ g, float* __restrict__ fc) {
    __shared__ __align__(16) float sf[NB*CIN*AA];
    int t = threadIdx.x;
    size_t nbase = (size_t)blockIdx.x * NB;

    {
        const float4* src = (const float4*)(fm + nbase * CIN * AA);
        float4* dst = (float4*)sf;
        const int TOT4 = NB*CIN*AA/4;
        for (int i = t; i < TOT4; i += blockDim.x) dst[i] = src[i];
    }
    __syncthreads();

    const int NITEMS = COUT * (NB/2);
    for (int item = t; item < NITEMS; item += blockDim.x) {
        int o     = item % COUT;
        int npair = item / COUT;
        const float* sf0 = sf + (npair*2 + 0) * CIN * AA;
        const float* sf1 = sf + (npair*2 + 1) * CIN * AA;

        unsigned long long sA0[6], sA1[6], cA0[6], cA1[6];
        float bias = bc[o];
        unsigned long long bpk = pack2(bias, bias);
#pragma unroll
        for (int j = 0; j < 6; j++) { sA0[j] = 0ULL; sA1[j] = 0ULL; cA0[j] = bpk; cA1[j] = bpk; }

        for (int c = 0; c < CIN; c++) {
            float ws = Ws[c*COUT + o];
            float wc = Wc[c*COUT + o];
            unsigned long long ws2 = pack2(ws, ws);
            unsigned long long wc2 = pack2(wc, wc);
            const ulonglong2* f0 = (const ulonglong2*)(sf0 + c*AA);
            const ulonglong2* f1 = (const ulonglong2*)(sf1 + c*AA);
#pragma unroll
            for (int h = 0; h < 3; h++) {
                ulonglong2 a = f0[h];
                sA0[h*2+0] = fma2(a.x, ws2, sA0[h*2+0]);
                sA0[h*2+1] = fma2(a.y, ws2, sA0[h*2+1]);
                cA0[h*2+0] = fma2(a.x, wc2, cA0[h*2+0]);
                cA0[h*2+1] = fma2(a.y, wc2, cA0[h*2+1]);
                ulonglong2 b = f1[h];
                sA1[h*2+0] = fma2(b.x, ws2, sA1[h*2+0]);
                sA1[h*2+1] = fma2(b.y, ws2, sA1[h*2+1]);
                cA1[h*2+0] = fma2(b.x, wc2, cA1[h*2+0]);
                cA1[h*2+1] = fma2(b.y, wc2, cA1[h*2+1]);
            }
        }

        size_t base0 = ((nbase + npair*2 + 0) * COUT + o) * AA;
        size_t base1 = ((nbase + npair*2 + 1) * COUT + o) * AA;
        unsigned long long* gp0 = (unsigned long long*)(g + base0);
        unsigned long long* gp1 = (unsigned long long*)(g + base1);
        unsigned long long* cp0 = (unsigned long long*)(fc + base0);
        unsigned long long* cp1 = (unsigned long long*)(fc + base1);
#pragma unroll
        for (int j = 0; j < 6; j++) {
            gp0[j] = sA0[j]; gp1[j] = sA1[j];
            cp0[j] = cA0[j]; cp1[j] = cA1[j];
        }
    }
}

// ---------------- neighbor: out = fc + max_k g[idx_k]*theta_k ----------------
// launch_bounds caps regs -> 4 blocks/SM; unroll-4 keeps 4 gathers in flight.
__global__ void __launch_bounds__(256, 4)
neighbor_kernel(const float* __restrict__ g, const float* __restrict__ fc,
                const float* __restrict__ v, const int* __restrict__ idx,
                const float* __restrict__ dirs,
                float* __restrict__ out, int npts, int cout) {
    int node = blockIdx.x;
    int b = node / npts;
    int t = threadIdx.x;
    __shared__ float sdir[KNN][3];
    __shared__ float sth[KNN][AA];
    __shared__ int   sidx[KNN];
    __shared__ float sdv[AA*3];

    if (t < AA*3) sdv[t] = dirs[t];
    if (t < KNN) {
        int m = idx[(size_t)node*KNN + t];
        sidx[t] = m;
        const float* pn = v + (size_t)node * 3;
        const float* pm = v + ((size_t)b*npts + m) * 3;
        float dx = pm[0]-pn[0], dy = pm[1]-pn[1], dz = pm[2]-pn[2];
        float den = sqrtf(dx*dx + dy*dy + dz*dz) + 1e-8f;
        sdir[t][0] = dx/den; sdir[t][1] = dy/den; sdir[t][2] = dz/den;
    }
    __syncthreads();
    if (t < KNN*AA) {
        int k = t / AA, a = t % AA;
        float d = sdir[k][0]*sdv[a*3+0] + sdir[k][1]*sdv[a*3+1] + sdir[k][2]*sdv[a*3+2];
        sth[k][a] = fmaxf(d, 0.0f);
    }
    __syncthreads();

    int tot = cout * AA;
    int tot4 = tot / 4;
    size_t out_off = (size_t)node * tot;
    for (int q = t; q < tot4; q += blockDim.x) {
        int base = q * 4;
        int a0 = base % AA;
        float4 m = make_float4(-INF_F, -INF_F, -INF_F, -INF_F);
#pragma unroll 4
        for (int k = 0; k < KNN; k++) {
            const float4 gv = *(const float4*)(g + ((size_t)b*npts + sidx[k])*tot + base);
            const float4 th = *(const float4*)(&sth[k][a0]);
            m.x = fmaxf(m.x, gv.x*th.x);
            m.y = fmaxf(m.y, gv.y*th.y);
            m.z = fmaxf(m.z, gv.z*th.z);
            m.w = fmaxf(m.w, gv.w*th.w);
        }
        float4 f = *(const float4*)(fc + out_off + base);
        *(float4*)(out + out_off + base) =
            make_float4(f.x+m.x, f.y+m.y, f.z+m.z, f.w+m.w);
    }
}

// ---------------- batchnorm stats: stage 1 (partial sums per slice) ----------------
__global__ void bn_part_kernel(const float* __restrict__ x, double* __restrict__ part,
                               int C, int npts) {
    int c = blockIdx.x;
    int s = blockIdx.y;
    int t = threadIdx.x;
    int nn = BB * npts;
    int nps = nn / NSLICE;
    double sm = 0.0, s2 = 0.0;
    for (int i = s*nps + t; i < (s+1)*nps; i += blockDim.x) {
        const float4* p = (const float4*)(x + ((size_t)i * C + c) * AA);
#pragma unroll
        for (int h = 0; h < 3; h++) {
            float4 v = p[h];
            double a = v.x, b = v.y, d = v.z, e = v.w;
            sm += a + b + d + e;
            s2 += a*a + b*b + d*d + e*e;
        }
    }
    __shared__ double sh[64], sh2[64];
    sh[t] = sm; sh2[t] = s2;
    __syncthreads();
    for (int st = 32; st > 0; st >>= 1) {
        if (t < st) { sh[t] += sh[t+st]; sh2[t] += sh2[t+st]; }
        __syncthreads();
    }
    if (t == 0) {
        part[(s*C + c)*2 + 0] = sh[0];
        part[(s*C + c)*2 + 1] = sh2[0];
    }
}

// ---------------- batchnorm stats: stage 2 (finalize scale/shift) ----------------
__global__ void bn_finalize_kernel(const double* __restrict__ part,
                                   const float* __restrict__ gamma, const float* __restrict__ beta,
                                   float* __restrict__ scale, float* __restrict__ shift,
                                   int C, int npts) {
    int c = threadIdx.x;
    if (c >= C) return;
    double s = 0.0, s2 = 0.0;
    for (int sl = 0; sl < NSLICE; sl++) {
        s  += part[(sl*C + c)*2 + 0];
        s2 += part[(sl*C + c)*2 + 1];
    }
    double cnt = (double)BB * npts * AA;
    double mean = s / cnt;
    double var  = s2 / cnt - mean * mean;
    float sc = gamma[c] * (float)(1.0 / sqrt(var + 1e-5));
    scale[c] = sc;
    shift[c] = beta[c] - (float)mean * sc;
}

// ---------------- fused bn apply + relu + fea (max over a) ----------------
__global__ void bn_fea_kernel(float* __restrict__ x,
                              const float* __restrict__ scale, const float* __restrict__ shift,
                              float* __restrict__ out, int C, int total_nc) {
    int i = blockIdx.x * blockDim.x + threadIdx.x;
    if (i >= total_nc) return;
    int c = i % C;
    float sc = scale[c], sh = shift[c];
    float4* p = (float4*)(x + (size_t)i * AA);
    float m = 0.0f;
#pragma unroll
    for (int j = 0; j < 3; j++) {
        float4 v = p[j];
        v.x = fmaxf(v.x*sc + sh, 0.f);
        v.y = fmaxf(v.y*sc + sh, 0.f);
        v.z = fmaxf(v.z*sc + sh, 0.f);
        v.w = fmaxf(v.w*sc + sh, 0.f);
        p[j] = v;
        m = fmaxf(m, fmaxf(fmaxf(v.x, v.y), fmaxf(v.z, v.w)));
    }
    out[i] = m;
}

// ---------------- pool ----------------
__global__ void pool_kernel(const float* __restrict__ v, const float* __restrict__ fm,
                            const int* __restrict__ idx,
                            float* __restrict__ v_out, float* __restrict__ fm_out,
                            int npts, int C) {
    int nsel = npts / 4;
    int bs = blockIdx.x;
    int b = bs / nsel, s = bs % nsel;
    int n = s * 4;
    size_t node = (size_t)b * npts + n;
    int t = threadIdx.x;
    __shared__ int sidx[4];
    if (t < 4) sidx[t] = idx[node*KNN + t];
    if (t < 3) v_out[((size_t)b*nsel + s)*3 + t] = v[node*3 + t];
    __syncthreads();
    int tot = C * AA;
    for (int i = t; i < tot; i += blockDim.x) {
        float m = fm[node*tot + i];
#pragma unroll
        for (int k = 0; k < 4; k++)
            m = fmaxf(m, fm[((size_t)b*npts + sidx[k])*tot + i]);
        fm_out[((size_t)b*nsel + s)*tot + i] = m;
    }
}

// ---------------- fea (no-BN layers) ----------------
__global__ void fea_kernel(const float* __restrict__ fm, float* __restrict__ out,
                           int C, int npts) {
    int i = blockIdx.x * blockDim.x + threadIdx.x;
    int total = BB * npts * C;
    if (i >= total) return;
    const float* p = fm + (size_t)i * AA;
    float m = p[0];
#pragma unroll
    for (int a = 1; a < AA; a++) m = fmaxf(m, p[a]);
    out[i] = m;
}

// ---------------- launch ----------------
extern "C" void kernel_launch(void* const* d_in, const int* in_sizes, int n_in,
                              void* d_out, int out_size) {
    const float* vertices = (const float*)d_in[0];
    const float* K0    = (const float*)d_in[1];
    const float* dirs1 = (const float*)d_in[2];
    const float* Wc1   = (const float*)d_in[3];
    const float* bc1   = (const float*)d_in[4];
    const float* Ws1   = (const float*)d_in[5];
    const float* dirs2 = (const float*)d_in[6];
    const float* Wc2   = (const float*)d_in[7];
    const float* bc2   = (const float*)d_in[8];
    const float* Ws2   = (const float*)d_in[9];
    const float* dirs3 = (const float*)d_in[10];
    const float* Wc3   = (const float*)d_in[11];
    const float* bc3   = (const float*)d_in[12];
    const float* Ws3   = (const float*)d_in[13];
    const float* dirs4 = (const float*)d_in[14];
    const float* Wc4   = (const float*)d_in[15];
    const float* bc4   = (const float*)d_in[16];
    const float* Ws4   = (const float*)d_in[17];
    const float* g1 = (const float*)d_in[18];
    const float* b1 = (const float*)d_in[19];
    const float* g2 = (const float*)d_in[20];
    const float* b2 = (const float*)d_in[21];
    const float* g3 = (const float*)d_in[22];
    const float* b3 = (const float*)d_in[23];
    float* out = (float*)d_out;

    float *fm0, *fm1, *fmp1, *fm2, *fm3, *fmp2, *fm4, *gbuf, *fcbuf, *v1, *v2, *bnscale, *bnshift;
    double *bnpart;
    int *idx0, *idx1, *idx2;
    cudaGetSymbolAddress((void**)&fm0,  d_fm0);
    cudaGetSymbolAddress((void**)&fm1,  d_fm1);
    cudaGetSymbolAddress((void**)&fmp1, d_fmp1);
    cudaGetSymbolAddress((void**)&fm2,  d_fm2);
    cudaGetSymbolAddress((void**)&fm3,  d_fm3);
    cudaGetSymbolAddress((void**)&fmp2, d_fmp2);
    cudaGetSymbolAddress((void**)&fm4,  d_fm4);
    cudaGetSymbolAddress((void**)&gbuf, d_gbuf);
    cudaGetSymbolAddress((void**)&fcbuf,d_fcbuf);
    cudaGetSymbolAddress((void**)&idx0, d_idx0);
    cudaGetSymbolAddress((void**)&idx1, d_idx1);
    cudaGetSymbolAddress((void**)&idx2, d_idx2);
    cudaGetSymbolAddress((void**)&v1,   d_v1);
    cudaGetSymbolAddress((void**)&v2,   d_v2);
    cudaGetSymbolAddress((void**)&bnscale, d_bnscale);
    cudaGetSymbolAddress((void**)&bnshift, d_bnshift);
    cudaGetSymbolAddress((void**)&bnpart,  d_bnpart);

    const size_t off0 = 0;
    const size_t off1 = off0 + (size_t)BB*N0*C0;
    const size_t off2 = off1 + (size_t)BB*N0*C1;
    const size_t off3 = off2 + (size_t)BB*N1*C2;
    const size_t off4 = off3 + (size_t)BB*N1*C3;

    // ---- stage 0 (fea0 fused into conv_surface) ----
    knn_kernel<<<dim3(N0/64, BB), 64>>>(vertices, idx0, N0);
    conv_surface_kernel<<<BB*N0, C0*AA>>>(vertices, idx0, K0, fm0, out + off0);

    // ---- layer 1: 32 -> 64 on 4096 ----
    proj_t_kernel<C0, C1, 16><<<(BB*N0)/16, 256>>>(fm0, Ws1, Wc1, bc1, gbuf, fcbuf);
    neighbor_kernel<<<BB*N0, 256>>>(gbuf, fcbuf, vertices, idx0, dirs1, fm1, N0, C1);
    bn_part_kernel<<<dim3(C1, NSLICE), 64>>>(fm1, bnpart, C1, N0);
    bn_finalize_kernel<<<1, 256>>>(bnpart, g1, b1, bnscale, bnshift, C1, N0);
    bn_fea_kernel<<<(BB*N0*C1 + 255)/256, 256>>>(fm1, bnscale, bnshift, out + off1, C1, BB*N0*C1);

    // ---- pool 1 + knn on 1024 ----
    pool_kernel<<<BB*N1, 256>>>(vertices, fm1, idx0, v1, fmp1, N0, C1);
    knn_kernel<<<dim3(N1/64, BB), 64>>>(v1, idx1, N1);

    // ---- layer 2: 64 -> 128 on 1024 ----
    proj_t_kernel<C1, C2, 8><<<(BB*N1)/8, 256>>>(fmp1, Ws2, Wc2, bc2, gbuf, fcbuf);
    neighbor_kernel<<<BB*N1, 256>>>(gbuf, fcbuf, v1, idx1, dirs2, fm2, N1, C2);
    bn_part_kernel<<<dim3(C2, NSLICE), 64>>>(fm2, bnpart, C2, N1);
    bn_finalize_kernel<<<1, 256>>>(bnpart, g2, b2, bnscale, bnshift, C2, N1);
    bn_fea_kernel<<<(BB*N1*C2 + 255)/256, 256>>>(fm2, bnscale, bnshift, out + off2, C2, BB*N1*C2);

    // ---- layer 3: 128 -> 256 on 1024 ----
    proj_t_kernel<C2, C3, 4><<<(BB*N1)/4, 256>>>(fm2, Ws3, Wc3, bc3, gbuf, fcbuf);
    neighbor_kernel<<<BB*N1, 256>>>(gbuf, fcbuf, v1, idx1, dirs3, fm3, N1, C3);
    bn_part_kernel<<<dim3(C3, NSLICE), 64>>>(fm3, bnpart, C3, N1);
    bn_finalize_kernel<<<1, 256>>>(bnpart, g3, b3, bnscale, bnshift, C3, N1);
    bn_fea_kernel<<<(BB*N1*C3 + 255)/256, 256>>>(fm3, bnscale, bnshift, out + off3, C3, BB*N1*C3);

    // ---- pool 2 + knn on 256 ----
    pool_kernel<<<BB*N2, 256>>>(v1, fm3, idx1, v2, fmp2, N1, C3);
    knn_kernel<<<dim3(N2/64, BB), 64>>>(v2, idx2, N2);

    // ---- layer 4: 256 -> 512 on 256 (no BN/relu) ----
    proj_t_kernel<C3, C4, 2><<<(BB*N2)/2, 256>>>(fmp2, Ws4, Wc4, bc4, gbuf, fcbuf);
    neighbor_kernel<<<BB*N2, 256>>>(gbuf, fcbuf, v2, idx2, dirs4, fm4, N2, C4);
    fea_kernel<<<(BB*N2*C4 + 255)/256, 256>>>(fm4, out + off4, C4, N2);
}